// round 10
// baseline (speedup 1.0000x reference)
#include <cuda_runtime.h>
#include <cuda_bf16.h>
#include <mma.h>
#include <math.h>

using namespace nvcuda;

// ---------------- problem constants ----------------
#define BB   16
#define NN   512
#define CC   768
#define HH   12
#define DD   64
#define HID  3072
#define MTOK (BB*NN)          // 8192
#define BH   (BB*HH)          // 192
#define QKV3 (3*CC)           // 2304

// ---------------- scratch (device globals; no cudaMalloc allowed) ----------
__device__ __nv_bfloat16 g_h   [(size_t)MTOK*CC];
__device__ __nv_bfloat16 g_wqkv[(size_t)QKV3*CC];
__device__ __nv_bfloat16 g_wproj[(size_t)CC*CC];
__device__ __nv_bfloat16 g_fc1t[(size_t)HID*CC];
__device__ __nv_bfloat16 g_fc1f[(size_t)HID*CC];
__device__ __nv_bfloat16 g_fc2t[(size_t)CC*HID];
__device__ __nv_bfloat16 g_fc2f[(size_t)CC*HID];
__device__ __nv_bfloat16 g_qkv [(size_t)MTOK*QKV3];
__device__ float         g_S   [(size_t)BH*NN*NN];   // 201 MB
__device__ __nv_bfloat16 g_P   [(size_t)BH*NN*NN];   // 101 MB
__device__ __nv_bfloat16 g_o   [(size_t)MTOK*CC];
__device__ float         g_x1  [(size_t)MTOK*CC];
__device__ __nv_bfloat16 g_h2  [(size_t)MTOK*CC];
__device__ __nv_bfloat16 g_hid [(size_t)MTOK*HID];

// ---------------- utility ----------------
__global__ void f2bf_kernel(const float* __restrict__ src, __nv_bfloat16* __restrict__ dst, size_t n) {
    size_t i = (size_t)blockIdx.x * blockDim.x + threadIdx.x;
    if (i < n) dst[i] = __float2bfloat16(src[i]);
}

// LayerNorm over C=768 -> bf16; g/b selected by (token%512)<256
__global__ void __launch_bounds__(256) ln_kernel(
    const float* __restrict__ x,
    const float* __restrict__ g0, const float* __restrict__ b0,
    const float* __restrict__ g1, const float* __restrict__ b1,
    __nv_bfloat16* __restrict__ out)
{
    int t = blockIdx.x;
    bool first = (t & (NN-1)) < 256;
    const float* g = first ? g0 : g1;
    const float* bb = first ? b0 : b1;
    const float* xr = x + (size_t)t * CC;
    int tid = threadIdx.x;
    float v0 = xr[tid], v1 = xr[tid+256], v2 = xr[tid+512];
    float s = v0+v1+v2;
    float q = v0*v0 + v1*v1 + v2*v2;
    __shared__ float rs[8], rq[8];
    #pragma unroll
    for (int o = 16; o > 0; o >>= 1) {
        s += __shfl_xor_sync(0xffffffffu, s, o);
        q += __shfl_xor_sync(0xffffffffu, q, o);
    }
    int wid = tid >> 5;
    if ((tid & 31) == 0) { rs[wid] = s; rq[wid] = q; }
    __syncthreads();
    float S = 0.f, Q = 0.f;
    #pragma unroll
    for (int w = 0; w < 8; w++) { S += rs[w]; Q += rq[w]; }
    float mean = S * (1.f/CC);
    float var  = Q * (1.f/CC) - mean*mean;
    float r = rsqrtf(var + 1e-5f);
    __nv_bfloat16* orow = out + (size_t)t * CC;
    orow[tid]     = __float2bfloat16((v0-mean)*r*g[tid]     + bb[tid]);
    orow[tid+256] = __float2bfloat16((v1-mean)*r*g[tid+256] + bb[tid+256]);
    orow[tid+512] = __float2bfloat16((v2-mean)*r*g[tid+512] + bb[tid+512]);
}

// fused scale + bias-gather + mask + softmax: fp32 S -> bf16 P
// mask read as 32-bit words (bool input is canonicalized to a 4-byte dtype)
__global__ void __launch_bounds__(128) softmax_kernel(
    const float* __restrict__ S,
    const int* __restrict__ rpi,
    const float* __restrict__ table,
    const unsigned int* __restrict__ mask,
    __nv_bfloat16* __restrict__ P)
{
    int row = blockIdx.x;                 // [0, BH*NN)
    int z = row >> 9;  int i = row & (NN-1);
    int b = z / HH;    int h = z % HH;
    const float* Sr = S + (size_t)row * NN;
    const int* ir = rpi + (size_t)i * NN;
    const unsigned int* mr = mask + (size_t)b * NN;
    int tid = threadIdx.x;
    float l[4];
    #pragma unroll
    for (int t = 0; t < 4; t++) {
        int j = tid + t*128;
        float vv = Sr[j] * 0.125f + table[ir[j]*HH + h];
        if (mr[j] == 0u) vv = -INFINITY;
        l[t] = vv;
    }
    __shared__ float rm[4], rsum[4];
    float m = fmaxf(fmaxf(l[0], l[1]), fmaxf(l[2], l[3]));
    #pragma unroll
    for (int o = 16; o > 0; o >>= 1) m = fmaxf(m, __shfl_xor_sync(0xffffffffu, m, o));
    int wid = tid >> 5;
    if ((tid & 31) == 0) rm[wid] = m;
    __syncthreads();
    m = fmaxf(fmaxf(rm[0], rm[1]), fmaxf(rm[2], rm[3]));
    float e[4]; float s = 0.f;
    #pragma unroll
    for (int t = 0; t < 4; t++) { e[t] = expf(l[t] - m); s += e[t]; }
    #pragma unroll
    for (int o = 16; o > 0; o >>= 1) s += __shfl_xor_sync(0xffffffffu, s, o);
    if ((tid & 31) == 0) rsum[wid] = s;
    __syncthreads();
    s = rsum[0] + rsum[1] + rsum[2] + rsum[3];
    float inv = 1.f / s;
    __nv_bfloat16* Pr = P + (size_t)row * NN;
    #pragma unroll
    for (int t = 0; t < 4; t++) Pr[tid + t*128] = __float2bfloat16(e[t] * inv);
}

// ---------------- generic bf16 WMMA GEMM ----------------
// C[M,N] = A[M,K] @ op(B) (+bias) (+epilogue), bf16 in, fp32 accum
//   BT=true : B stored [N,K] row-major (A @ B^T);  BT=false: B [K,N]
// EPI: 0 plain store (OUTF32 picks dtype), 1 bias+exact GELU (bf16 out),
//      2 bias + X + gamma*val (fp32 out)
// split-weight by (m0 % 512) >= 256; batch z: zb=z/divH, zh=z%divH (divH=0 -> zh=z)
#define BM 128
#define BN 64
#define BKK 32

template<bool BT, bool OUTF32, int EPI>
__global__ void __launch_bounds__(256) gemm_kernel(
    const __nv_bfloat16* __restrict__ A,
    const __nv_bfloat16* __restrict__ B0,
    const __nv_bfloat16* __restrict__ B1,
    const float* __restrict__ bias0,
    const float* __restrict__ bias1,
    void* __restrict__ Cout,
    const float* __restrict__ X,
    const float* __restrict__ gamma,
    int K, int lda, int ldb, int ldc,
    int divH,
    size_t sAb, size_t sAh,
    size_t sBb, size_t sBh,
    size_t sCb, size_t sCh)
{
    __shared__ __align__(16) unsigned char smem_raw[34816];
    __nv_bfloat16* As = (__nv_bfloat16*)smem_raw;            // [BM][40]
    __nv_bfloat16* Bs = (__nv_bfloat16*)(smem_raw + 10240);  // BT:[BN][40] / !BT:[BKK][72]
    float* Cs = (float*)smem_raw;                            // [BM][68]

    int z = blockIdx.z;
    int zb = divH > 0 ? z / divH : 0;
    int zh = divH > 0 ? z % divH : z;
    const __nv_bfloat16* Ap = A + zb*sAb + zh*sAh;
    int m0 = blockIdx.y * BM;
    int n0 = blockIdx.x * BN;
    bool second = ((m0 & (NN-1)) >= 256);
    const __nv_bfloat16* Bp = (second ? B1 : B0) + zb*sBb + zh*sBh;
    const float* bias = second ? bias1 : bias0;

    int tid = threadIdx.x;
    int wid = tid >> 5;
    int wm = wid & 3;          // 4 warps along M
    int wn = wid >> 2;         // 2 warps along N

    wmma::fragment<wmma::accumulator, 16, 16, 16, float> cf[2][2];
    #pragma unroll
    for (int i = 0; i < 2; i++)
        #pragma unroll
        for (int j = 0; j < 2; j++)
            wmma::fill_fragment(cf[i][j], 0.f);

    for (int kt = 0; kt < K; kt += BKK) {
        #pragma unroll
        for (int vv = 0; vv < 4; vv++) {
            int vi = tid + vv * 256;
            int row = vi >> 3;
            int c4 = (vi & 7) * 4;
            *(uint2*)&As[row*40 + c4] =
                *(const uint2*)&Ap[(size_t)(m0+row)*lda + kt + c4];
        }
        if (BT) {
            #pragma unroll
            for (int vv = 0; vv < 2; vv++) {
                int vi = tid + vv * 256;
                int row = vi >> 3;
                int c4 = (vi & 7) * 4;
                *(uint2*)&Bs[row*40 + c4] =
                    *(const uint2*)&Bp[(size_t)(n0+row)*ldb + kt + c4];
            }
        } else {
            #pragma unroll
            for (int vv = 0; vv < 2; vv++) {
                int vi = tid + vv * 256;
                int row = vi >> 4;
                int c4 = (vi & 15) * 4;
                *(uint2*)&Bs[row*72 + c4] =
                    *(const uint2*)&Bp[(size_t)(kt+row)*ldb + n0 + c4];
            }
        }
        __syncthreads();

        #pragma unroll
        for (int kk = 0; kk < BKK; kk += 16) {
            wmma::fragment<wmma::matrix_a, 16,16,16, __nv_bfloat16, wmma::row_major> af[2];
            #pragma unroll
            for (int i = 0; i < 2; i++)
                wmma::load_matrix_sync(af[i], &As[(wm*32 + i*16)*40 + kk], 40);
            if (BT) {
                wmma::fragment<wmma::matrix_b, 16,16,16, __nv_bfloat16, wmma::col_major> bf[2];
                #pragma unroll
                for (int j = 0; j < 2; j++)
                    wmma::load_matrix_sync(bf[j], &Bs[(wn*32 + j*16)*40 + kk], 40);
                #pragma unroll
                for (int i = 0; i < 2; i++)
                    #pragma unroll
                    for (int j = 0; j < 2; j++)
                        wmma::mma_sync(cf[i][j], af[i], bf[j], cf[i][j]);
            } else {
                wmma::fragment<wmma::matrix_b, 16,16,16, __nv_bfloat16, wmma::row_major> bf[2];
                #pragma unroll
                for (int j = 0; j < 2; j++)
                    wmma::load_matrix_sync(bf[j], &Bs[kk*72 + wn*32 + j*16], 72);
                #pragma unroll
                for (int i = 0; i < 2; i++)
                    #pragma unroll
                    for (int j = 0; j < 2; j++)
                        wmma::mma_sync(cf[i][j], af[i], bf[j], cf[i][j]);
            }
        }
        __syncthreads();
    }

    #pragma unroll
    for (int i = 0; i < 2; i++)
        #pragma unroll
        for (int j = 0; j < 2; j++)
            wmma::store_matrix_sync(&Cs[(wm*32 + i*16)*68 + wn*32 + j*16],
                                    cf[i][j], 68, wmma::mem_row_major);
    __syncthreads();

    size_t zoff = zb*sCb + zh*sCh;

    #pragma unroll
    for (int e = 0; e < 32; e++) {
        int f = e * 256 + tid;
        int r = f >> 6;
        int c = f & 63;
        float acc = Cs[r*68 + c];
        int gn = n0 + c;
        size_t off = zoff + (size_t)(m0 + r) * ldc + gn;
        if (EPI == 0) {
            if (OUTF32) ((float*)Cout)[off] = acc;
            else        ((__nv_bfloat16*)Cout)[off] = __float2bfloat16(acc);
        } else if (EPI == 1) {
            float vv = acc + bias[gn];
            vv = 0.5f * vv * (1.f + erff(vv * 0.70710678118654752f));
            ((__nv_bfloat16*)Cout)[off] = __float2bfloat16(vv);
        } else {
            float vv = acc + bias[gn];
            ((float*)Cout)[off] = X[off] + gamma[gn] * vv;
        }
    }
}

// ---------------- host launcher ----------------
static inline void conv_w(const float* src, __nv_bfloat16* dst, size_t n) {
    f2bf_kernel<<<(unsigned)((n + 255) / 256), 256>>>(src, dst, n);
}

extern "C" void kernel_launch(void* const* d_in, const int* in_sizes, int n_in,
                              void* d_out, int out_size)
{
    const float* x        = (const float*)d_in[0];
    const unsigned int* mask = (const unsigned int*)d_in[1];
    const int* rpi        = (const int*)d_in[2];
    const float* W_qkv    = (const float*)d_in[3];
    const float* W_proj   = (const float*)d_in[4];
    const float* b_proj   = (const float*)d_in[5];
    const float* rel_table= (const float*)d_in[6];
    const float* ln1_g    = (const float*)d_in[7];
    const float* ln1_b    = (const float*)d_in[8];
    const float* gamma1   = (const float*)d_in[9];
    const float* gamma2   = (const float*)d_in[10];
    const float* ln2t_g   = (const float*)d_in[11];
    const float* ln2t_b   = (const float*)d_in[12];
    const float* fc1t_W   = (const float*)d_in[13];
    const float* fc1t_b   = (const float*)d_in[14];
    const float* fc2t_W   = (const float*)d_in[15];
    const float* fc2t_b   = (const float*)d_in[16];
    const float* ln2f_g   = (const float*)d_in[17];
    const float* ln2f_b   = (const float*)d_in[18];
    const float* fc1f_W   = (const float*)d_in[19];
    const float* fc1f_b   = (const float*)d_in[20];
    const float* fc2f_W   = (const float*)d_in[21];
    const float* fc2f_b   = (const float*)d_in[22];
    float* out = (float*)d_out;

    __nv_bfloat16 *p_h, *p_wqkv, *p_wproj, *p_fc1t, *p_fc1f, *p_fc2t, *p_fc2f;
    __nv_bfloat16 *p_qkv, *p_P, *p_o, *p_h2, *p_hid;
    float *p_S, *p_x1;
    cudaGetSymbolAddress((void**)&p_h,    g_h);
    cudaGetSymbolAddress((void**)&p_wqkv, g_wqkv);
    cudaGetSymbolAddress((void**)&p_wproj,g_wproj);
    cudaGetSymbolAddress((void**)&p_fc1t, g_fc1t);
    cudaGetSymbolAddress((void**)&p_fc1f, g_fc1f);
    cudaGetSymbolAddress((void**)&p_fc2t, g_fc2t);
    cudaGetSymbolAddress((void**)&p_fc2f, g_fc2f);
    cudaGetSymbolAddress((void**)&p_qkv,  g_qkv);
    cudaGetSymbolAddress((void**)&p_S,    g_S);
    cudaGetSymbolAddress((void**)&p_P,    g_P);
    cudaGetSymbolAddress((void**)&p_o,    g_o);
    cudaGetSymbolAddress((void**)&p_x1,   g_x1);
    cudaGetSymbolAddress((void**)&p_h2,   g_h2);
    cudaGetSymbolAddress((void**)&p_hid,  g_hid);

    // 0. weights -> bf16
    conv_w(W_qkv,  p_wqkv,  (size_t)QKV3*CC);
    conv_w(W_proj, p_wproj, (size_t)CC*CC);
    conv_w(fc1t_W, p_fc1t,  (size_t)HID*CC);
    conv_w(fc1f_W, p_fc1f,  (size_t)HID*CC);
    conv_w(fc2t_W, p_fc2t,  (size_t)CC*HID);
    conv_w(fc2f_W, p_fc2f,  (size_t)CC*HID);

    // 1. LN1 -> bf16 h
    ln_kernel<<<MTOK, 256>>>(x, ln1_g, ln1_b, ln1_g, ln1_b, p_h);

    // 2. QKV GEMM: [8192,768] @ [2304,768]^T -> bf16 [8192,2304]
    gemm_kernel<true,false,0><<<dim3(QKV3/BN, MTOK/BM, 1), 256>>>(
        p_h, p_wqkv, p_wqkv, nullptr, nullptr, p_qkv, nullptr, nullptr,
        CC, CC, CC, QKV3, 0, 0,0, 0,0, 0,0);

    // 3. scores: per (b,h): S = q @ k^T (unscaled) -> fp32, z = 192
    gemm_kernel<true,true,0><<<dim3(NN/BN, NN/BM, BH), 256>>>(
        p_qkv, p_qkv + CC, p_qkv + CC, nullptr, nullptr, p_S, nullptr, nullptr,
        DD, QKV3, QKV3, NN, HH,
        (size_t)NN*QKV3, (size_t)DD,
        (size_t)NN*QKV3, (size_t)DD,
        (size_t)HH*NN*NN, (size_t)NN*NN);

    // 4. scale + bias + mask + softmax -> bf16 P
    softmax_kernel<<<BH*NN, 128>>>(p_S, rpi, rel_table, mask, p_P);

    // 5. PV: P[512,512] @ V[512,64] -> scattered into [B,N,C] bf16
    gemm_kernel<false,false,0><<<dim3(DD/BN, NN/BM, BH), 256>>>(
        p_P, p_qkv + 2*CC, p_qkv + 2*CC, nullptr, nullptr, p_o, nullptr, nullptr,
        NN, NN, QKV3, CC, HH,
        (size_t)HH*NN*NN, (size_t)NN*NN,
        (size_t)NN*QKV3, (size_t)DD,
        (size_t)NN*CC, (size_t)DD);

    // 6. proj + residual: x1 = x + gamma1*(o @ Wp^T + b) -> fp32
    gemm_kernel<true,true,2><<<dim3(CC/BN, MTOK/BM, 1), 256>>>(
        p_o, p_wproj, p_wproj, b_proj, b_proj, p_x1, x, gamma1,
        CC, CC, CC, CC, 0, 0,0, 0,0, 0,0);

    // 7. LN2 (split t/f) -> bf16 h2
    ln_kernel<<<MTOK, 256>>>(p_x1, ln2t_g, ln2t_b, ln2f_g, ln2f_b, p_h2);

    // 8. fc1 + GELU (split weights) -> bf16 hid [8192,3072]
    gemm_kernel<true,false,1><<<dim3(HID/BN, MTOK/BM, 1), 256>>>(
        p_h2, p_fc1t, p_fc1f, fc1t_b, fc1f_b, p_hid, nullptr, nullptr,
        CC, CC, CC, HID, 0, 0,0, 0,0, 0,0);

    // 9. fc2 + residual -> final fp32 output
    gemm_kernel<true,true,2><<<dim3(CC/BN, MTOK/BM, 1), 256>>>(
        p_hid, p_fc2t, p_fc2f, fc2t_b, fc2f_b, out, p_x1, gamma2,
        HID, HID, HID, CC, 0, 0,0, 0,0, 0,0);
}

// round 14
// speedup vs baseline: 1.2285x; 1.2285x over previous
#include <cuda_runtime.h>
#include <cuda_bf16.h>
#include <mma.h>
#include <math.h>

using namespace nvcuda;

// ---------------- problem constants ----------------
#define BB   16
#define NN   512
#define CC   768
#define HH   12
#define DD   64
#define HID  3072
#define MTOK (BB*NN)          // 8192
#define BH   (BB*HH)          // 192
#define QKV3 (3*CC)           // 2304

// ---------------- scratch ----------------
__device__ __nv_bfloat16 g_h   [(size_t)MTOK*CC];
__device__ __nv_bfloat16 g_wqkv[(size_t)QKV3*CC];
__device__ __nv_bfloat16 g_wproj[(size_t)CC*CC];
__device__ __nv_bfloat16 g_fc1t[(size_t)HID*CC];
__device__ __nv_bfloat16 g_fc1f[(size_t)HID*CC];
__device__ __nv_bfloat16 g_fc2t[(size_t)CC*HID];
__device__ __nv_bfloat16 g_fc2f[(size_t)CC*HID];
__device__ __nv_bfloat16 g_qkv [(size_t)MTOK*QKV3];
__device__ float         g_S   [(size_t)BH*NN*NN];
__device__ __nv_bfloat16 g_P   [(size_t)BH*NN*NN];
__device__ __nv_bfloat16 g_o   [(size_t)MTOK*CC];
__device__ float         g_x1  [(size_t)MTOK*CC];
__device__ __nv_bfloat16 g_h2  [(size_t)MTOK*CC];
__device__ __nv_bfloat16 g_hid [(size_t)MTOK*HID];

// ---------------- utility ----------------
__global__ void f2bf_kernel(const float* __restrict__ src, __nv_bfloat16* __restrict__ dst, size_t n) {
    size_t i = (size_t)blockIdx.x * blockDim.x + threadIdx.x;
    if (i < n) dst[i] = __float2bfloat16(src[i]);
}

__global__ void __launch_bounds__(256) ln_kernel(
    const float* __restrict__ x,
    const float* __restrict__ g0, const float* __restrict__ b0,
    const float* __restrict__ g1, const float* __restrict__ b1,
    __nv_bfloat16* __restrict__ out)
{
    int t = blockIdx.x;
    bool first = (t & (NN-1)) < 256;
    const float* g = first ? g0 : g1;
    const float* bb = first ? b0 : b1;
    const float* xr = x + (size_t)t * CC;
    int tid = threadIdx.x;
    float v0 = xr[tid], v1 = xr[tid+256], v2 = xr[tid+512];
    float s = v0+v1+v2;
    float q = v0*v0 + v1*v1 + v2*v2;
    __shared__ float rs[8], rq[8];
    #pragma unroll
    for (int o = 16; o > 0; o >>= 1) {
        s += __shfl_xor_sync(0xffffffffu, s, o);
        q += __shfl_xor_sync(0xffffffffu, q, o);
    }
    int wid = tid >> 5;
    if ((tid & 31) == 0) { rs[wid] = s; rq[wid] = q; }
    __syncthreads();
    float S = 0.f, Q = 0.f;
    #pragma unroll
    for (int w = 0; w < 8; w++) { S += rs[w]; Q += rq[w]; }
    float mean = S * (1.f/CC);
    float var  = Q * (1.f/CC) - mean*mean;
    float r = rsqrtf(var + 1e-5f);
    __nv_bfloat16* orow = out + (size_t)t * CC;
    orow[tid]     = __float2bfloat16((v0-mean)*r*g[tid]     + bb[tid]);
    orow[tid+256] = __float2bfloat16((v1-mean)*r*g[tid+256] + bb[tid+256]);
    orow[tid+512] = __float2bfloat16((v2-mean)*r*g[tid+512] + bb[tid+512]);
}

// mask read as 32-bit words (bool canonicalized to 4-byte dtype)
__global__ void __launch_bounds__(128) softmax_kernel(
    const float* __restrict__ S,
    const int* __restrict__ rpi,
    const float* __restrict__ table,
    const unsigned int* __restrict__ mask,
    __nv_bfloat16* __restrict__ P)
{
    int row = blockIdx.x;
    int z = row >> 9;  int i = row & (NN-1);
    int b = z / HH;    int h = z % HH;
    const float* Sr = S + (size_t)row * NN;
    const int* ir = rpi + (size_t)i * NN;
    const unsigned int* mr = mask + (size_t)b * NN;
    int tid = threadIdx.x;
    float l[4];
    #pragma unroll
    for (int t = 0; t < 4; t++) {
        int j = tid + t*128;
        float vv = Sr[j] * 0.125f + table[ir[j]*HH + h];
        if (mr[j] == 0u) vv = -INFINITY;
        l[t] = vv;
    }
    __shared__ float rm[4], rsum[4];
    float m = fmaxf(fmaxf(l[0], l[1]), fmaxf(l[2], l[3]));
    #pragma unroll
    for (int o = 16; o > 0; o >>= 1) m = fmaxf(m, __shfl_xor_sync(0xffffffffu, m, o));
    int wid = tid >> 5;
    if ((tid & 31) == 0) rm[wid] = m;
    __syncthreads();
    m = fmaxf(fmaxf(rm[0], rm[1]), fmaxf(rm[2], rm[3]));
    float e[4]; float s = 0.f;
    #pragma unroll
    for (int t = 0; t < 4; t++) { e[t] = expf(l[t] - m); s += e[t]; }
    #pragma unroll
    for (int o = 16; o > 0; o >>= 1) s += __shfl_xor_sync(0xffffffffu, s, o);
    if ((tid & 31) == 0) rsum[wid] = s;
    __syncthreads();
    s = rsum[0] + rsum[1] + rsum[2] + rsum[3];
    float inv = 1.f / s;
    __nv_bfloat16* Pr = P + (size_t)row * NN;
    #pragma unroll
    for (int t = 0; t < 4; t++) Pr[tid + t*128] = __float2bfloat16(e[t] * inv);
}

// ---------------- cp.async helpers ----------------
__device__ __forceinline__ void cp16(void* dst, const void* src) {
    unsigned d = (unsigned)__cvta_generic_to_shared(dst);
    asm volatile("cp.async.cg.shared.global [%0], [%1], 16;\n" :: "r"(d), "l"(src));
}
#define CP_COMMIT() asm volatile("cp.async.commit_group;\n" ::: "memory")

// ---------------- pipelined bf16 WMMA GEMM ----------------
// C[M,N] = A[M,K] @ op(B) (+bias)(+epilogue); bf16 in, fp32 accum
// BT: B [N,K] (A@B^T); !BT: B [K,N]
// EPI: 0 plain (OUTF32 dtype), 1 bias+GELU (bf16), 2 bias+X+gamma*val (fp32)
// split-weight by (m0 % 512) >= 256; batch z: zb=z/divH, zh=z%divH
#define BM 128
#define BKK 32

template<bool BT, bool OUTF32, int EPI, int BN_, int STAGES>
__global__ void __launch_bounds__(256) gemm2(
    const __nv_bfloat16* __restrict__ A,
    const __nv_bfloat16* __restrict__ B0,
    const __nv_bfloat16* __restrict__ B1,
    const float* __restrict__ bias0,
    const float* __restrict__ bias1,
    void* __restrict__ Cout,
    const float* __restrict__ X,
    const float* __restrict__ gamma,
    int K, int lda, int ldb, int ldc, int divH,
    size_t sAb, size_t sAh,
    size_t sBb, size_t sBh,
    size_t sCb, size_t sCh)
{
    extern __shared__ __align__(16) unsigned char dyn[];
    constexpr int A_BYTES = BM * 40 * 2;                         // [128][40] bf16
    constexpr int B_BYTES = BT ? BN_ * 40 * 2 : BKK * (BN_ + 8) * 2;
    constexpr int STAGE   = A_BYTES + B_BYTES;
    constexpr int NF      = BN_ / 32;                            // frags per warp in N
    constexpr int BCH     = (BN_ * 4) / 256;                     // B chunks per thread

    int z = blockIdx.z;
    int zb = divH > 0 ? z / divH : 0;
    int zh = divH > 0 ? z % divH : z;
    const __nv_bfloat16* Ap = A + zb*sAb + zh*sAh;
    int m0 = blockIdx.y * BM;
    int n0 = blockIdx.x * BN_;
    bool second = ((m0 & (NN-1)) >= 256);
    const __nv_bfloat16* Bp = (second ? B1 : B0) + zb*sBb + zh*sBh;
    const float* bias = second ? bias1 : bias0;

    int tid = threadIdx.x;
    int wid = tid >> 5;
    int wm = wid & 3;
    int wn = wid >> 2;

    wmma::fragment<wmma::accumulator, 16, 16, 16, float> cf[2][NF];
    #pragma unroll
    for (int i = 0; i < 2; i++)
        #pragma unroll
        for (int j = 0; j < NF; j++)
            wmma::fill_fragment(cf[i][j], 0.f);

    auto load_stage = [&](int s, int kt) {
        __nv_bfloat16* As = (__nv_bfloat16*)(dyn + (size_t)s * STAGE);
        __nv_bfloat16* Bs = (__nv_bfloat16*)(dyn + (size_t)s * STAGE + A_BYTES);
        #pragma unroll
        for (int i = 0; i < 2; i++) {
            int id = tid + i * 256;
            int r = id >> 2, c = (id & 3) * 8;
            cp16(&As[r*40 + c], &Ap[(size_t)(m0 + r)*lda + kt + c]);
        }
        if (BT) {
            #pragma unroll
            for (int i = 0; i < BCH; i++) {
                int id = tid + i * 256;
                int r = id >> 2, c = (id & 3) * 8;
                cp16(&Bs[r*40 + c], &Bp[(size_t)(n0 + r)*ldb + kt + c]);
            }
        } else {
            #pragma unroll
            for (int i = 0; i < BCH; i++) {
                int id = tid + i * 256;
                int r = id / (BN_/8), c = (id % (BN_/8)) * 8;
                cp16(&Bs[r*(BN_+8) + c], &Bp[(size_t)(kt + r)*ldb + n0 + c]);
            }
        }
    };

    int KT = K / BKK;
    #pragma unroll
    for (int s = 0; s < STAGES - 1; s++) {
        if (s < KT) load_stage(s, s * BKK);
        CP_COMMIT();
    }

    for (int kt = 0; kt < KT; kt++) {
        asm volatile("cp.async.wait_group %0;\n" :: "n"(STAGES - 2) : "memory");
        __syncthreads();
        int pf = kt + STAGES - 1;
        if (pf < KT) load_stage(pf % STAGES, pf * BKK);
        CP_COMMIT();

        int s = kt % STAGES;
        __nv_bfloat16* As = (__nv_bfloat16*)(dyn + (size_t)s * STAGE);
        __nv_bfloat16* Bs = (__nv_bfloat16*)(dyn + (size_t)s * STAGE + A_BYTES);

        #pragma unroll
        for (int kk = 0; kk < BKK; kk += 16) {
            wmma::fragment<wmma::matrix_a, 16,16,16, __nv_bfloat16, wmma::row_major> af[2];
            #pragma unroll
            for (int i = 0; i < 2; i++)
                wmma::load_matrix_sync(af[i], &As[(wm*32 + i*16)*40 + kk], 40);
            if (BT) {
                wmma::fragment<wmma::matrix_b, 16,16,16, __nv_bfloat16, wmma::col_major> bfr[NF];
                #pragma unroll
                for (int j = 0; j < NF; j++)
                    wmma::load_matrix_sync(bfr[j], &Bs[(wn*(BN_/2) + j*16)*40 + kk], 40);
                #pragma unroll
                for (int i = 0; i < 2; i++)
                    #pragma unroll
                    for (int j = 0; j < NF; j++)
                        wmma::mma_sync(cf[i][j], af[i], bfr[j], cf[i][j]);
            } else {
                wmma::fragment<wmma::matrix_b, 16,16,16, __nv_bfloat16, wmma::row_major> bfr[NF];
                #pragma unroll
                for (int j = 0; j < NF; j++)
                    wmma::load_matrix_sync(bfr[j], &Bs[kk*(BN_+8) + wn*(BN_/2) + j*16], BN_+8);
                #pragma unroll
                for (int i = 0; i < 2; i++)
                    #pragma unroll
                    for (int j = 0; j < NF; j++)
                        wmma::mma_sync(cf[i][j], af[i], bfr[j], cf[i][j]);
            }
        }
    }

    asm volatile("cp.async.wait_all;\n" ::: "memory");
    __syncthreads();

    // epilogue: stage accumulators in smem (reuses pipeline buffers)
    float* Cs = (float*)dyn;                                     // [BM][BN_+4]
    #pragma unroll
    for (int i = 0; i < 2; i++)
        #pragma unroll
        for (int j = 0; j < NF; j++)
            wmma::store_matrix_sync(&Cs[(wm*32 + i*16)*(BN_+4) + wn*(BN_/2) + j*16],
                                    cf[i][j], BN_+4, wmma::mem_row_major);
    __syncthreads();

    size_t zoff = zb*sCb + zh*sCh;
    constexpr int EPT = BM * BN_ / 256;
    #pragma unroll
    for (int e = 0; e < EPT; e++) {
        int f = e * 256 + tid;
        int r = f / BN_;
        int c = f % BN_;
        float acc = Cs[r*(BN_+4) + c];
        int gn = n0 + c;
        size_t off = zoff + (size_t)(m0 + r) * ldc + gn;
        if (EPI == 0) {
            if (OUTF32) ((float*)Cout)[off] = acc;
            else        ((__nv_bfloat16*)Cout)[off] = __float2bfloat16(acc);
        } else if (EPI == 1) {
            float vv = acc + bias[gn];
            vv = 0.5f * vv * (1.f + erff(vv * 0.70710678118654752f));
            ((__nv_bfloat16*)Cout)[off] = __float2bfloat16(vv);
        } else {
            float vv = acc + bias[gn];
            ((float*)Cout)[off] = X[off] + gamma[gn] * vv;
        }
    }
}

// ---------------- host ----------------
static inline void conv_w(const float* src, __nv_bfloat16* dst, size_t n) {
    f2bf_kernel<<<(unsigned)((n + 255) / 256), 256>>>(src, dst, n);
}

template<bool BT, int BN_, int STAGES>
static inline int smem_for() {
    int a = BM*40*2;
    int b = BT ? BN_*40*2 : BKK*(BN_+8)*2;
    int main_b = STAGES * (a + b);
    int epi_b  = BM * (BN_+4) * 4;
    return main_b > epi_b ? main_b : epi_b;
}

extern "C" void kernel_launch(void* const* d_in, const int* in_sizes, int n_in,
                              void* d_out, int out_size)
{
    const float* x        = (const float*)d_in[0];
    const unsigned int* mask = (const unsigned int*)d_in[1];
    const int* rpi        = (const int*)d_in[2];
    const float* W_qkv    = (const float*)d_in[3];
    const float* W_proj   = (const float*)d_in[4];
    const float* b_proj   = (const float*)d_in[5];
    const float* rel_table= (const float*)d_in[6];
    const float* ln1_g    = (const float*)d_in[7];
    const float* ln1_b    = (const float*)d_in[8];
    const float* gamma1   = (const float*)d_in[9];
    const float* gamma2   = (const float*)d_in[10];
    const float* ln2t_g   = (const float*)d_in[11];
    const float* ln2t_b   = (const float*)d_in[12];
    const float* fc1t_W   = (const float*)d_in[13];
    const float* fc1t_b   = (const float*)d_in[14];
    const float* fc2t_W   = (const float*)d_in[15];
    const float* fc2t_b   = (const float*)d_in[16];
    const float* ln2f_g   = (const float*)d_in[17];
    const float* ln2f_b   = (const float*)d_in[18];
    const float* fc1f_W   = (const float*)d_in[19];
    const float* fc1f_b   = (const float*)d_in[20];
    const float* fc2f_W   = (const float*)d_in[21];
    const float* fc2f_b   = (const float*)d_in[22];
    float* out = (float*)d_out;

    __nv_bfloat16 *p_h, *p_wqkv, *p_wproj, *p_fc1t, *p_fc1f, *p_fc2t, *p_fc2f;
    __nv_bfloat16 *p_qkv, *p_P, *p_o, *p_h2, *p_hid;
    float *p_S, *p_x1;
    cudaGetSymbolAddress((void**)&p_h,    g_h);
    cudaGetSymbolAddress((void**)&p_wqkv, g_wqkv);
    cudaGetSymbolAddress((void**)&p_wproj,g_wproj);
    cudaGetSymbolAddress((void**)&p_fc1t, g_fc1t);
    cudaGetSymbolAddress((void**)&p_fc1f, g_fc1f);
    cudaGetSymbolAddress((void**)&p_fc2t, g_fc2t);
    cudaGetSymbolAddress((void**)&p_fc2f, g_fc2f);
    cudaGetSymbolAddress((void**)&p_qkv,  g_qkv);
    cudaGetSymbolAddress((void**)&p_S,    g_S);
    cudaGetSymbolAddress((void**)&p_P,    g_P);
    cudaGetSymbolAddress((void**)&p_o,    g_o);
    cudaGetSymbolAddress((void**)&p_x1,   g_x1);
    cudaGetSymbolAddress((void**)&p_h2,   g_h2);
    cudaGetSymbolAddress((void**)&p_hid,  g_hid);

    // set dynamic smem caps (idempotent)
    const int SM_T128 = smem_for<true,128,4>();
    const int SM_F64  = smem_for<false,64,4>();
    cudaFuncSetAttribute(gemm2<true,false,0,128,4>, cudaFuncAttributeMaxDynamicSharedMemorySize, SM_T128);
    cudaFuncSetAttribute(gemm2<true,true, 0,128,4>, cudaFuncAttributeMaxDynamicSharedMemorySize, SM_T128);
    cudaFuncSetAttribute(gemm2<false,false,0,64,4>, cudaFuncAttributeMaxDynamicSharedMemorySize, SM_F64);
    cudaFuncSetAttribute(gemm2<true,true, 2,128,4>, cudaFuncAttributeMaxDynamicSharedMemorySize, SM_T128);
    cudaFuncSetAttribute(gemm2<true,false,1,128,4>, cudaFuncAttributeMaxDynamicSharedMemorySize, SM_T128);

    // 0. weights -> bf16
    conv_w(W_qkv,  p_wqkv,  (size_t)QKV3*CC);
    conv_w(W_proj, p_wproj, (size_t)CC*CC);
    conv_w(fc1t_W, p_fc1t,  (size_t)HID*CC);
    conv_w(fc1f_W, p_fc1f,  (size_t)HID*CC);
    conv_w(fc2t_W, p_fc2t,  (size_t)CC*HID);
    conv_w(fc2f_W, p_fc2f,  (size_t)CC*HID);

    // 1. LN1
    ln_kernel<<<MTOK, 256>>>(x, ln1_g, ln1_b, ln1_g, ln1_b, p_h);

    // 2. QKV: [8192,768] @ [2304,768]^T -> bf16
    gemm2<true,false,0,128,4><<<dim3(QKV3/128, MTOK/BM, 1), 256, SM_T128>>>(
        p_h, p_wqkv, p_wqkv, nullptr, nullptr, p_qkv, nullptr, nullptr,
        CC, CC, CC, QKV3, 0, 0,0, 0,0, 0,0);

    // 3. scores: S = q @ k^T per (b,h), z=192
    gemm2<true,true,0,128,4><<<dim3(NN/128, NN/BM, BH), 256, SM_T128>>>(
        p_qkv, p_qkv + CC, p_qkv + CC, nullptr, nullptr, p_S, nullptr, nullptr,
        DD, QKV3, QKV3, NN, HH,
        (size_t)NN*QKV3, (size_t)DD,
        (size_t)NN*QKV3, (size_t)DD,
        (size_t)HH*NN*NN, (size_t)NN*NN);

    // 4. softmax
    softmax_kernel<<<BH*NN, 128>>>(p_S, rpi, rel_table, mask, p_P);

    // 5. PV: P @ V -> scattered [B,N,C] bf16
    gemm2<false,false,0,64,4><<<dim3(DD/64, NN/BM, BH), 256, SM_F64>>>(
        p_P, p_qkv + 2*CC, p_qkv + 2*CC, nullptr, nullptr, p_o, nullptr, nullptr,
        NN, NN, QKV3, CC, HH,
        (size_t)HH*NN*NN, (size_t)NN*NN,
        (size_t)NN*QKV3, (size_t)DD,
        (size_t)NN*CC, (size_t)DD);

    // 6. proj + residual
    gemm2<true,true,2,128,4><<<dim3(CC/128, MTOK/BM, 1), 256, SM_T128>>>(
        p_o, p_wproj, p_wproj, b_proj, b_proj, p_x1, x, gamma1,
        CC, CC, CC, CC, 0, 0,0, 0,0, 0,0);

    // 7. LN2
    ln_kernel<<<MTOK, 256>>>(p_x1, ln2t_g, ln2t_b, ln2f_g, ln2f_b, p_h2);

    // 8. fc1 + GELU
    gemm2<true,false,1,128,4><<<dim3(HID/128, MTOK/BM, 1), 256, SM_T128>>>(
        p_h2, p_fc1t, p_fc1f, fc1t_b, fc1f_b, p_hid, nullptr, nullptr,
        CC, CC, CC, HID, 0, 0,0, 0,0, 0,0);

    // 9. fc2 + residual -> out
    gemm2<true,true,2,128,4><<<dim3(CC/128, MTOK/BM, 1), 256, SM_T128>>>(
        p_hid, p_fc2t, p_fc2f, fc2t_b, fc2f_b, out, p_x1, gamma2,
        HID, HID, HID, CC, 0, 0,0, 0,0, 0,0);
}